// round 3
// baseline (speedup 1.0000x reference)
#include <cuda_runtime.h>
#include <math.h>

// Problem dims (fixed by the reference):
//   joint_feature      [B, D] = [1024, 1024]
//   confounder_dict    [K, D] = [256, 1024]
//   prior              [K, 1]
//   Wq, Wk             [D, P] = [1024, 768]
//   out                [B, D]
#define BB 1024
#define KK 256
#define DD 1024
#define PP 768

// Scratch (device globals — no allocations allowed in kernel_launch)
__device__ float g_q[BB * PP];    // q = joint @ Wq           [1024, 768]
__device__ float g_k[KK * PP];    // k = conf  @ Wk           [256, 768]
__device__ float g_cp[KK * DD];   // conf * prior             [256, 1024]
__device__ float g_s[BB * KK];    // scores -> attn           [1024, 256]

// ---------------------------------------------------------------------------
// Tiled SGEMM: C[M,N] = alpha * A[M,Kd] @ B[Kd,N]  (+ Cadd[M,N] if WITH_ADD)
// 128x128 block tile, Kd-chunk 8, 256 threads, 8x8 per-thread micro-tile.
// All dims must divide tiles (true for every call here).
// ---------------------------------------------------------------------------
template <bool WITH_ADD>
__global__ __launch_bounds__(256, 2) void gemm_nn(
    const float* __restrict__ A, const float* __restrict__ B,
    const float* __restrict__ Cadd, float* __restrict__ C,
    int M, int N, int Kd, float alpha)
{
    __shared__ float As[8][128];
    __shared__ float Bs[8][128];

    const int tid = threadIdx.x;
    const int tx = tid & 15;          // 0..15 -> col micro-tile
    const int ty = tid >> 4;          // 0..15 -> row micro-tile
    const int row0 = blockIdx.y * 128;
    const int col0 = blockIdx.x * 128;

    // A-tile load map: one float4 per thread per k-chunk
    const int ar = tid >> 1;              // 0..127
    const int ac = (tid & 1) * 4;         // 0 or 4
    // B-tile load map
    const int bk = tid >> 5;              // 0..7
    const int bc = (tid & 31) * 4;        // 0..124

    float acc[8][8];
    #pragma unroll
    for (int i = 0; i < 8; i++)
        #pragma unroll
        for (int j = 0; j < 8; j++) acc[i][j] = 0.f;

    for (int k0 = 0; k0 < Kd; k0 += 8) {
        float4 av = *reinterpret_cast<const float4*>(
            &A[(size_t)(row0 + ar) * Kd + k0 + ac]);
        As[ac + 0][ar] = av.x;
        As[ac + 1][ar] = av.y;
        As[ac + 2][ar] = av.z;
        As[ac + 3][ar] = av.w;
        float4 bv = *reinterpret_cast<const float4*>(
            &B[(size_t)(k0 + bk) * N + col0 + bc]);
        *reinterpret_cast<float4*>(&Bs[bk][bc]) = bv;
        __syncthreads();

        #pragma unroll
        for (int kk = 0; kk < 8; kk++) {
            float a[8], b[8];
            #pragma unroll
            for (int i = 0; i < 8; i++) a[i] = As[kk][ty * 8 + i];
            #pragma unroll
            for (int j = 0; j < 8; j++) b[j] = Bs[kk][tx * 8 + j];
            #pragma unroll
            for (int i = 0; i < 8; i++)
                #pragma unroll
                for (int j = 0; j < 8; j++) acc[i][j] += a[i] * b[j];
        }
        __syncthreads();
    }

    #pragma unroll
    for (int i = 0; i < 8; i++) {
        const int r = row0 + ty * 8 + i;
        #pragma unroll
        for (int j = 0; j < 8; j++) {
            const int c = col0 + tx * 8 + j;
            float v = alpha * acc[i][j];
            if (WITH_ADD) v += Cadd[(size_t)r * N + c];
            C[(size_t)r * N + c] = v;
        }
    }
}

// ---------------------------------------------------------------------------
// C[M,N] = alpha * A[M,Kd] @ B^T   with B stored [N,Kd] row-major (scores GEMM)
// ---------------------------------------------------------------------------
__global__ __launch_bounds__(256, 2) void gemm_nt(
    const float* __restrict__ A, const float* __restrict__ B,
    float* __restrict__ C, int M, int N, int Kd, float alpha)
{
    __shared__ float As[8][128];
    __shared__ float Bs[8][128];

    const int tid = threadIdx.x;
    const int tx = tid & 15;
    const int ty = tid >> 4;
    const int row0 = blockIdx.y * 128;
    const int col0 = blockIdx.x * 128;

    const int ar = tid >> 1;
    const int ac = (tid & 1) * 4;
    const int bn = tid >> 1;          // 0..127 (n within tile)
    const int bkc = (tid & 1) * 4;    // k offset 0 or 4

    float acc[8][8];
    #pragma unroll
    for (int i = 0; i < 8; i++)
        #pragma unroll
        for (int j = 0; j < 8; j++) acc[i][j] = 0.f;

    for (int k0 = 0; k0 < Kd; k0 += 8) {
        float4 av = *reinterpret_cast<const float4*>(
            &A[(size_t)(row0 + ar) * Kd + k0 + ac]);
        As[ac + 0][ar] = av.x;
        As[ac + 1][ar] = av.y;
        As[ac + 2][ar] = av.z;
        As[ac + 3][ar] = av.w;
        float4 bv = *reinterpret_cast<const float4*>(
            &B[(size_t)(col0 + bn) * Kd + k0 + bkc]);
        Bs[bkc + 0][bn] = bv.x;
        Bs[bkc + 1][bn] = bv.y;
        Bs[bkc + 2][bn] = bv.z;
        Bs[bkc + 3][bn] = bv.w;
        __syncthreads();

        #pragma unroll
        for (int kk = 0; kk < 8; kk++) {
            float a[8], b[8];
            #pragma unroll
            for (int i = 0; i < 8; i++) a[i] = As[kk][ty * 8 + i];
            #pragma unroll
            for (int j = 0; j < 8; j++) b[j] = Bs[kk][tx * 8 + j];
            #pragma unroll
            for (int i = 0; i < 8; i++)
                #pragma unroll
                for (int j = 0; j < 8; j++) acc[i][j] += a[i] * b[j];
        }
        __syncthreads();
    }

    #pragma unroll
    for (int i = 0; i < 8; i++) {
        const int r = row0 + ty * 8 + i;
        #pragma unroll
        for (int j = 0; j < 8; j++) {
            const int c = col0 + tx * 8 + j;
            C[(size_t)r * N + c] = alpha * acc[i][j];
        }
    }
}

// conf * prior  (broadcast prior over D)
__global__ void prep_cp(const float* __restrict__ conf,
                        const float* __restrict__ prior,
                        float* __restrict__ cp)
{
    int i = blockIdx.x * blockDim.x + threadIdx.x;  // over K*D
    int k = i >> 10;   // / DD
    cp[i] = conf[i] * prior[k];
}

// Row softmax over K=256: one block per row, 256 threads.
__global__ __launch_bounds__(256) void softmax_rows(float* __restrict__ s)
{
    const int b = blockIdx.x;
    const int t = threadIdx.x;
    __shared__ float red[8];
    __shared__ float bcast;

    float v = s[(size_t)b * KK + t];

    // max reduce
    float m = v;
    #pragma unroll
    for (int o = 16; o; o >>= 1) m = fmaxf(m, __shfl_xor_sync(~0u, m, o));
    if ((t & 31) == 0) red[t >> 5] = m;
    __syncthreads();
    if (t == 0) {
        float x = red[0];
        #pragma unroll
        for (int w = 1; w < 8; w++) x = fmaxf(x, red[w]);
        bcast = x;
    }
    __syncthreads();
    const float rowmax = bcast;

    float e = __expf(v - rowmax);

    // sum reduce
    float sm = e;
    #pragma unroll
    for (int o = 16; o; o >>= 1) sm += __shfl_xor_sync(~0u, sm, o);
    if ((t & 31) == 0) red[t >> 5] = sm;
    __syncthreads();
    if (t == 0) {
        float x = 0.f;
        #pragma unroll
        for (int w = 0; w < 8; w++) x += red[w];
        bcast = x;
    }
    __syncthreads();

    s[(size_t)b * KK + t] = e / bcast;
}

extern "C" void kernel_launch(void* const* d_in, const int* in_sizes, int n_in,
                              void* d_out, int out_size)
{
    const float* joint = (const float*)d_in[0];   // [1024,1024]
    const float* conf  = (const float*)d_in[1];   // [256,1024]
    const float* prior = (const float*)d_in[2];   // [256,1]
    const float* Wq    = (const float*)d_in[3];   // [1024,768]
    const float* Wk    = (const float*)d_in[4];   // [1024,768]
    float* out = (float*)d_out;                   // [1024,1024]

    float* q;  cudaGetSymbolAddress((void**)&q,  g_q);
    float* k;  cudaGetSymbolAddress((void**)&k,  g_k);
    float* cp; cudaGetSymbolAddress((void**)&cp, g_cp);
    float* s;  cudaGetSymbolAddress((void**)&s,  g_s);

    const float scale = 1.0f / 32.0f;  // 1/sqrt(1024)

    // q = joint @ Wq              [1024,768]
    gemm_nn<false><<<dim3(PP / 128, BB / 128), 256>>>(joint, Wq, nullptr, q,
                                                      BB, PP, DD, 1.0f);
    // k = conf @ Wk               [256,768]
    gemm_nn<false><<<dim3(PP / 128, KK / 128), 256>>>(conf, Wk, nullptr, k,
                                                      KK, PP, DD, 1.0f);
    // cp = conf * prior           [256,1024]
    prep_cp<<<(KK * DD) / 256, 256>>>(conf, prior, cp);

    // scores = (q @ k^T) * scale  [1024,256]
    gemm_nt<<<dim3(KK / 128, BB / 128), 256>>>(q, k, s, BB, KK, PP, scale);

    // softmax rows
    softmax_rows<<<BB, 256>>>(s);

    // out = attn @ cp + joint     [1024,1024]
    gemm_nn<true><<<dim3(DD / 128, BB / 128), 256>>>(s, cp, joint, out,
                                                     BB, DD, KK, 1.0f);
}

// round 5
// speedup vs baseline: 6.7922x; 6.7922x over previous
#include <cuda_runtime.h>
#include <cuda_bf16.h>
#include <cstdint>
#include <math.h>

// Dims fixed by the reference
#define BB 1024
#define KK 256
#define DD 1024
#define PP 768

typedef __nv_bfloat16 bf16;

// ---------------- scratch (device globals; no allocs allowed) ----------------
__device__ bf16  g_jh [BB * DD];   // joint (bf16)                [1024,1024]
__device__ bf16  g_ch [KK * DD];   // conf  (bf16)                [256,1024]
__device__ bf16  g_wqt[PP * DD];   // Wq^T  (bf16)                [768,1024]
__device__ bf16  g_wkt[PP * DD];   // Wk^T  (bf16)                [768,1024]
__device__ bf16  g_cpt[DD * KK];   // (conf*prior)^T (bf16)       [1024,256]
__device__ bf16  g_qh [BB * PP];   // q (bf16)                    [1024,768]
__device__ bf16  g_kh [KK * PP];   // k (bf16)                    [256,768]
__device__ float g_s  [BB * KK];   // scores (fp32)               [1024,256]
__device__ bf16  g_ah [BB * KK];   // attn (bf16)                 [1024,256]

// ---------------- helpers ----------------------------------------------------
__device__ __forceinline__ uint32_t smem_u32(const void* p) {
    uint32_t a;
    asm("{ .reg .u64 t; cvta.to.shared.u64 t, %1; cvt.u32.u64 %0, t; }"
        : "=r"(a) : "l"(p));
    return a;
}

#define SWZ(off) ((off) ^ (((off) >> 3) & 0x70))

__device__ __forceinline__ void cp_async16(uint32_t dst, const void* src) {
    asm volatile("cp.async.cg.shared.global [%0], [%1], 16;"
                 :: "r"(dst), "l"(src));
}
#define CP_COMMIT() asm volatile("cp.async.commit_group;" ::: "memory")

__device__ __forceinline__ void ldm_x4(uint32_t* r, uint32_t addr) {
    asm volatile("ldmatrix.sync.aligned.m8n8.x4.shared.b16 {%0,%1,%2,%3}, [%4];"
                 : "=r"(r[0]), "=r"(r[1]), "=r"(r[2]), "=r"(r[3]) : "r"(addr));
}

__device__ __forceinline__ void mma16816(float* c, const uint32_t* a,
                                         uint32_t b0, uint32_t b1) {
    asm volatile(
        "mma.sync.aligned.m16n8k16.row.col.f32.bf16.bf16.f32 "
        "{%0,%1,%2,%3}, {%4,%5,%6,%7}, {%8,%9}, {%0,%1,%2,%3};"
        : "+f"(c[0]), "+f"(c[1]), "+f"(c[2]), "+f"(c[3])
        : "r"(a[0]), "r"(a[1]), "r"(a[2]), "r"(a[3]), "r"(b0), "r"(b1));
}

// ---------------------------------------------------------------------------
// bf16 tensor-core GEMM:  C[M,N] = A[M,Ka] · B[N,Ka]^T   (both K-major)
// Block tile 128x128, 256 threads = 8 warps (4 over M x 2 over N),
// warp tile 32x64, K-chunk 64, cp.async double-buffered SW128 SMEM.
// EPI: 0 = store bf16   1 = store fp32 * alpha   2 = store fp32 + Cadd
// ---------------------------------------------------------------------------
#define EPI_BF16  0
#define EPI_SCALE 1
#define EPI_ADD   2
#define STAGE_BYTES 32768  // 16KB A + 16KB B

template <int EPI>
__global__ __launch_bounds__(256) void gemm_mma(
    const bf16* __restrict__ A, const bf16* __restrict__ B,
    const float* __restrict__ Cadd, void* __restrict__ Cout,
    int Ka, int Nout, int nchunk, float alpha)
{
    extern __shared__ char smem[];
    const uint32_t sb = smem_u32(smem);
    const int tid  = threadIdx.x;
    const int wid  = tid >> 5, lane = tid & 31;
    const int wm   = wid & 3;          // 4 warps over M: rows wm*32..+31
    const int wn   = wid >> 2;         // 2 warps over N: cols wn*64..+63
    const int row0 = blockIdx.y * 128, col0 = blockIdx.x * 128;

    // global load mapping: 1024 16B segments per operand, 4 per thread
    // seg s: row = s>>3 (0..127), kseg = s&7 (16B units within 128B row)
    const int g  = lane >> 3;          // ldmatrix lane group 0..3
    const int l8 = lane & 7;

    // A-fragment ldmatrix row/koff per lane (within warp tile, per m16 tile)
    const int a_row  = wm * 32 + (g & 1) * 8 + l8;   // + mi*16
    const int a_koff = (g >> 1) * 8;                  // bf16 units
    // B pair-of-n8-tiles ldmatrix mapping (per pair pi: n tiles 2pi,2pi+1)
    const int b_row  = wn * 64 + (g >> 1) * 8 + l8;  // + pi*16
    const int b_koff = (g & 1) * 8;

    float acc[2][8][4];
    #pragma unroll
    for (int mi = 0; mi < 2; mi++)
        #pragma unroll
        for (int ni = 0; ni < 8; ni++)
            #pragma unroll
            for (int j = 0; j < 4; j++) acc[mi][ni][j] = 0.f;

    auto load_chunk = [&](int c, int buf) {
        const uint32_t st = sb + buf * STAGE_BYTES;
        const bf16* gA = A + (size_t)row0 * Ka + c * 64;
        const bf16* gB = B + (size_t)col0 * Ka + c * 64;
        #pragma unroll
        for (int i = 0; i < 4; i++) {
            int s = tid + i * 256;
            int r = s >> 3, ks = s & 7;
            uint32_t off = SWZ((uint32_t)(r * 128 + ks * 16));
            cp_async16(st + off,          gA + (size_t)r * Ka + ks * 8);
            cp_async16(st + 16384 + off,  gB + (size_t)r * Ka + ks * 8);
        }
        CP_COMMIT();
    };

    load_chunk(0, 0);

    for (int c = 0; c < nchunk; c++) {
        const int buf = c & 1;
        if (c + 1 < nchunk) {
            load_chunk(c + 1, buf ^ 1);
            asm volatile("cp.async.wait_group 1;" ::: "memory");
        } else {
            asm volatile("cp.async.wait_group 0;" ::: "memory");
        }
        __syncthreads();

        const uint32_t stA = sb + buf * STAGE_BYTES;
        const uint32_t stB = stA + 16384;

        #pragma unroll
        for (int k16 = 0; k16 < 4; k16++) {
            const int kb = k16 * 16;  // bf16 units
            uint32_t a[2][4];
            #pragma unroll
            for (int mi = 0; mi < 2; mi++) {
                uint32_t off = SWZ((uint32_t)((a_row + mi * 16) * 128 +
                                              (kb + a_koff) * 2));
                ldm_x4(a[mi], stA + off);
            }
            uint32_t b[4][4];
            #pragma unroll
            for (int pi = 0; pi < 4; pi++) {
                uint32_t off = SWZ((uint32_t)((b_row + pi * 16) * 128 +
                                              (kb + b_koff) * 2));
                ldm_x4(b[pi], stB + off);
            }
            #pragma unroll
            for (int mi = 0; mi < 2; mi++)
                #pragma unroll
                for (int ni = 0; ni < 8; ni++)
                    mma16816(acc[mi][ni], a[mi],
                             b[ni >> 1][(ni & 1) * 2],
                             b[ni >> 1][(ni & 1) * 2 + 1]);
        }
        __syncthreads();
    }

    // ---- epilogue: fragment c0,c1 at (row=grp, col=tig*2), c2,c3 at row+8 ----
    const int grp = lane >> 2, tig = lane & 3;
    const int rbase = row0 + wm * 32 + grp;
    const int cbase = col0 + wn * 64 + tig * 2;
    #pragma unroll
    for (int mi = 0; mi < 2; mi++) {
        #pragma unroll
        for (int ni = 0; ni < 8; ni++) {
            const int cc = cbase + ni * 8;
            const int r1 = rbase + mi * 16, r2 = r1 + 8;
            float* f = acc[mi][ni];
            if (EPI == EPI_BF16) {
                bf16* o = (bf16*)Cout;
                *(__nv_bfloat162*)&o[(size_t)r1 * Nout + cc] =
                    __floats2bfloat162_rn(f[0], f[1]);
                *(__nv_bfloat162*)&o[(size_t)r2 * Nout + cc] =
                    __floats2bfloat162_rn(f[2], f[3]);
            } else if (EPI == EPI_SCALE) {
                float* o = (float*)Cout;
                *(float2*)&o[(size_t)r1 * Nout + cc] =
                    make_float2(alpha * f[0], alpha * f[1]);
                *(float2*)&o[(size_t)r2 * Nout + cc] =
                    make_float2(alpha * f[2], alpha * f[3]);
            } else {
                float* o = (float*)Cout;
                float2 x = *(const float2*)&Cadd[(size_t)r1 * Nout + cc];
                float2 y = *(const float2*)&Cadd[(size_t)r2 * Nout + cc];
                *(float2*)&o[(size_t)r1 * Nout + cc] =
                    make_float2(f[0] + x.x, f[1] + x.y);
                *(float2*)&o[(size_t)r2 * Nout + cc] =
                    make_float2(f[2] + y.x, f[3] + y.y);
            }
        }
    }
}

// ---------------------------------------------------------------------------
// prep kernels
// ---------------------------------------------------------------------------
__global__ void cvt_bf16(const float* __restrict__ in, bf16* __restrict__ out, int n)
{
    int i = (blockIdx.x * blockDim.x + threadIdx.x) * 4;
    if (i < n) {
        float4 v = *(const float4*)&in[i];
        *(__nv_bfloat162*)&out[i]     = __floats2bfloat162_rn(v.x, v.y);
        *(__nv_bfloat162*)&out[i + 2] = __floats2bfloat162_rn(v.z, v.w);
    }
}

// Transpose + convert: out[c*R + r] = (bf16) in[r*C + c]
__global__ void transpose_cvt(const float* __restrict__ in, bf16* __restrict__ out,
                              int R, int C)
{
    __shared__ float t[32][33];
    const int c0 = blockIdx.x * 32, r0 = blockIdx.y * 32;
    #pragma unroll
    for (int j = 0; j < 32; j += 8)
        t[threadIdx.y + j][threadIdx.x] =
            in[(size_t)(r0 + threadIdx.y + j) * C + c0 + threadIdx.x];
    __syncthreads();
    #pragma unroll
    for (int j = 0; j < 32; j += 8)
        out[(size_t)(c0 + threadIdx.y + j) * R + r0 + threadIdx.x] =
            __float2bfloat16(t[threadIdx.x][threadIdx.y + j]);
}

// (conf * prior)^T -> bf16:  out[d*KK + k] = conf[k*DD + d] * prior[k]
__global__ void cpt_kernel(const float* __restrict__ conf,
                           const float* __restrict__ prior,
                           bf16* __restrict__ out)
{
    __shared__ float t[32][33];
    const int d0 = blockIdx.x * 32, k0 = blockIdx.y * 32;
    #pragma unroll
    for (int j = 0; j < 32; j += 8) {
        int k = k0 + threadIdx.y + j;
        t[threadIdx.y + j][threadIdx.x] =
            conf[(size_t)k * DD + d0 + threadIdx.x] * prior[k];
    }
    __syncthreads();
    #pragma unroll
    for (int j = 0; j < 32; j += 8)
        out[(size_t)(d0 + threadIdx.y + j) * KK + k0 + threadIdx.x] =
            __float2bfloat16(t[threadIdx.x][threadIdx.y + j]);
}

// Row softmax over K=256 (fp32 in, bf16 out). One block per row.
__global__ __launch_bounds__(256) void softmax_rows(const float* __restrict__ s,
                                                    bf16* __restrict__ a)
{
    const int b = blockIdx.x;
    const int t = threadIdx.x;
    __shared__ float red[8];
    __shared__ float bcast;

    float v = s[(size_t)b * KK + t];

    float m = v;
    #pragma unroll
    for (int o = 16; o; o >>= 1) m = fmaxf(m, __shfl_xor_sync(~0u, m, o));
    if ((t & 31) == 0) red[t >> 5] = m;
    __syncthreads();
    if (t == 0) {
        float x = red[0];
        #pragma unroll
        for (int w = 1; w < 8; w++) x = fmaxf(x, red[w]);
        bcast = x;
    }
    __syncthreads();
    const float rowmax = bcast;

    float e = __expf(v - rowmax);

    float sm = e;
    #pragma unroll
    for (int o = 16; o; o >>= 1) sm += __shfl_xor_sync(~0u, sm, o);
    if ((t & 31) == 0) red[t >> 5] = sm;
    __syncthreads();
    if (t == 0) {
        float x = 0.f;
        #pragma unroll
        for (int w = 0; w < 8; w++) x += red[w];
        bcast = x;
    }
    __syncthreads();

    a[(size_t)b * KK + t] = __float2bfloat16(e / bcast);
}

// ---------------------------------------------------------------------------
extern "C" void kernel_launch(void* const* d_in, const int* in_sizes, int n_in,
                              void* d_out, int out_size)
{
    const float* joint = (const float*)d_in[0];   // [1024,1024]
    const float* conf  = (const float*)d_in[1];   // [256,1024]
    const float* prior = (const float*)d_in[2];   // [256,1]
    const float* Wq    = (const float*)d_in[3];   // [1024,768]
    const float* Wk    = (const float*)d_in[4];   // [1024,768]
    float* out = (float*)d_out;                   // [1024,1024]

    bf16 *jh, *ch, *wqt, *wkt, *cpt, *qh, *kh, *ah; float* s;
    cudaGetSymbolAddress((void**)&jh,  g_jh);
    cudaGetSymbolAddress((void**)&ch,  g_ch);
    cudaGetSymbolAddress((void**)&wqt, g_wqt);
    cudaGetSymbolAddress((void**)&wkt, g_wkt);
    cudaGetSymbolAddress((void**)&cpt, g_cpt);
    cudaGetSymbolAddress((void**)&qh,  g_qh);
    cudaGetSymbolAddress((void**)&kh,  g_kh);
    cudaGetSymbolAddress((void**)&s,   g_s);
    cudaGetSymbolAddress((void**)&ah,  g_ah);

    const int SMEM = 2 * STAGE_BYTES;  // 64 KB
    cudaFuncSetAttribute(gemm_mma<EPI_BF16>,
                         cudaFuncAttributeMaxDynamicSharedMemorySize, SMEM);
    cudaFuncSetAttribute(gemm_mma<EPI_SCALE>,
                         cudaFuncAttributeMaxDynamicSharedMemorySize, SMEM);
    cudaFuncSetAttribute(gemm_mma<EPI_ADD>,
                         cudaFuncAttributeMaxDynamicSharedMemorySize, SMEM);

    // --- input conversions / transposes (bf16) ---
    cvt_bf16<<<(BB * DD) / 1024, 256>>>(joint, jh, BB * DD);
    cvt_bf16<<<(KK * DD) / 1024, 256>>>(conf, ch, KK * DD);
    transpose_cvt<<<dim3(PP / 32, DD / 32), dim3(32, 8)>>>(Wq, wqt, DD, PP);
    transpose_cvt<<<dim3(PP / 32, DD / 32), dim3(32, 8)>>>(Wk, wkt, DD, PP);
    cpt_kernel<<<dim3(DD / 32, KK / 32), dim3(32, 8)>>>(conf, prior, cpt);

    // --- q = joint @ Wq ---
    gemm_mma<EPI_BF16><<<dim3(PP / 128, BB / 128), 256, SMEM>>>(
        jh, wqt, nullptr, qh, DD, PP, DD / 64, 1.f);
    // --- k = conf @ Wk ---
    gemm_mma<EPI_BF16><<<dim3(PP / 128, KK / 128), 256, SMEM>>>(
        ch, wkt, nullptr, kh, DD, PP, DD / 64, 1.f);
    // --- scores = (q @ k^T)/32 ---
    gemm_mma<EPI_SCALE><<<dim3(KK / 128, BB / 128), 256, SMEM>>>(
        qh, kh, nullptr, s, PP, KK, PP / 64, 1.f / 32.f);
    // --- softmax rows (fp32 -> bf16 attn) ---
    softmax_rows<<<BB, 256>>>(s, ah);
    // --- out = attn @ (conf*prior) + joint ---
    gemm_mma<EPI_ADD><<<dim3(DD / 128, BB / 128), 256, SMEM>>>(
        ah, cpt, joint, out, KK, DD, KK / 64, 1.f);
}

// round 7
// speedup vs baseline: 12.0129x; 1.7686x over previous
#include <cuda_runtime.h>
#include <cuda_bf16.h>
#include <cstdint>
#include <math.h>

// Dims fixed by the reference
#define BB 1024
#define KK 256
#define DD 1024
#define PP 768

typedef __nv_bfloat16 bf16;

// ---------------- scratch (device globals; no allocs allowed) ----------------
__device__ bf16  g_jh [BB * DD];   // joint (bf16)                [1024,1024]
__device__ bf16  g_ch [KK * DD];   // conf  (bf16)                [256,1024]
__device__ bf16  g_wqt[PP * DD];   // Wq^T  (bf16)                [768,1024]
__device__ bf16  g_wkt[PP * DD];   // Wk^T  (bf16)                [768,1024]
__device__ bf16  g_cpt[DD * KK];   // (conf*prior)^T (bf16)       [1024,256]
__device__ bf16  g_qh [BB * PP];   // q (bf16)                    [1024,768]
__device__ bf16  g_kh [KK * PP];   // k (bf16)                    [256,768]
__device__ float g_s  [BB * KK];   // scores (fp32)               [1024,256]
__device__ bf16  g_ah [BB * KK];   // attn (bf16)                 [1024,256]

// ---------------- helpers ----------------------------------------------------
__device__ __forceinline__ uint32_t smem_u32(const void* p) {
    uint32_t a;
    asm("{ .reg .u64 t; cvta.to.shared.u64 t, %1; cvt.u32.u64 %0, t; }"
        : "=r"(a) : "l"(p));
    return a;
}

#define SWZ(off) ((off) ^ (((off) >> 3) & 0x70))

__device__ __forceinline__ void cp_async16(uint32_t dst, const void* src) {
    asm volatile("cp.async.cg.shared.global [%0], [%1], 16;"
                 :: "r"(dst), "l"(src));
}
#define CP_COMMIT() asm volatile("cp.async.commit_group;" ::: "memory")

__device__ __forceinline__ void ldm_x4(uint32_t* r, uint32_t addr) {
    asm volatile("ldmatrix.sync.aligned.m8n8.x4.shared.b16 {%0,%1,%2,%3}, [%4];"
                 : "=r"(r[0]), "=r"(r[1]), "=r"(r[2]), "=r"(r[3]) : "r"(addr));
}

__device__ __forceinline__ void mma16816(float* c, const uint32_t* a,
                                         uint32_t b0, uint32_t b1) {
    asm volatile(
        "mma.sync.aligned.m16n8k16.row.col.f32.bf16.bf16.f32 "
        "{%0,%1,%2,%3}, {%4,%5,%6,%7}, {%8,%9}, {%0,%1,%2,%3};"
        : "+f"(c[0]), "+f"(c[1]), "+f"(c[2]), "+f"(c[3])
        : "r"(a[0]), "r"(a[1]), "r"(a[2]), "r"(a[3]), "r"(b0), "r"(b1));
}

// ---------------------------------------------------------------------------
// bf16 tensor-core GEMM:  C[M,N] = A[M,Ka] · B[N,Ka]^T   (both K-major)
// Block tile 64x64, 128 threads = 4 warps (2 over M x 2 over N),
// warp tile 32x32, K-chunk 64, cp.async double-buffered SW128 SMEM.
// EPI: 0 = store bf16   1 = store fp32 * alpha   2 = store fp32 + Cadd
// ---------------------------------------------------------------------------
#define EPI_BF16  0
#define EPI_SCALE 1
#define EPI_ADD   2
#define STAGE_BYTES 16384  // 8KB A + 8KB B

template <int EPI>
__global__ __launch_bounds__(128) void gemm_mma(
    const bf16* __restrict__ A, const bf16* __restrict__ B,
    const float* __restrict__ Cadd, void* __restrict__ Cout,
    int Ka, int Nout, int nchunk, float alpha)
{
    extern __shared__ char smem[];
    const uint32_t sb = smem_u32(smem);
    const int tid  = threadIdx.x;
    const int wid  = tid >> 5, lane = tid & 31;
    const int wm   = wid & 1;          // 2 warps over M: rows wm*32..+31
    const int wn   = wid >> 1;         // 2 warps over N: cols wn*32..+31
    const int row0 = blockIdx.y * 64, col0 = blockIdx.x * 64;

    const int g  = lane >> 3;          // ldmatrix lane group 0..3
    const int l8 = lane & 7;

    // A-fragment ldmatrix row/koff per lane (within block tile, per m16 tile)
    const int a_row  = wm * 32 + (g & 1) * 8 + l8;   // + mi*16
    const int a_koff = (g >> 1) * 8;                  // bf16 units
    // B pair-of-n8-tiles ldmatrix mapping (per pair pi: n16 group)
    const int b_row  = wn * 32 + (g >> 1) * 8 + l8;  // + pi*16
    const int b_koff = (g & 1) * 8;

    float acc[2][4][4];
    #pragma unroll
    for (int mi = 0; mi < 2; mi++)
        #pragma unroll
        for (int ni = 0; ni < 4; ni++)
            #pragma unroll
            for (int j = 0; j < 4; j++) acc[mi][ni][j] = 0.f;

    auto load_chunk = [&](int c, int buf) {
        const uint32_t st = sb + buf * STAGE_BYTES;
        const bf16* gA = A + (size_t)row0 * Ka + c * 64;
        const bf16* gB = B + (size_t)col0 * Ka + c * 64;
        // 512 16B segments per operand, 4 per thread
        #pragma unroll
        for (int i = 0; i < 4; i++) {
            int s = tid + i * 128;
            int r = s >> 3, ks = s & 7;
            uint32_t off = SWZ((uint32_t)(r * 128 + ks * 16));
            cp_async16(st + off,         gA + (size_t)r * Ka + ks * 8);
            cp_async16(st + 8192 + off,  gB + (size_t)r * Ka + ks * 8);
        }
        CP_COMMIT();
    };

    load_chunk(0, 0);

    for (int c = 0; c < nchunk; c++) {
        const int buf = c & 1;
        if (c + 1 < nchunk) {
            load_chunk(c + 1, buf ^ 1);
            asm volatile("cp.async.wait_group 1;" ::: "memory");
        } else {
            asm volatile("cp.async.wait_group 0;" ::: "memory");
        }
        __syncthreads();

        const uint32_t stA = sb + buf * STAGE_BYTES;
        const uint32_t stB = stA + 8192;

        #pragma unroll
        for (int k16 = 0; k16 < 4; k16++) {
            const int kb = k16 * 16;  // bf16 units
            uint32_t a[2][4];
            #pragma unroll
            for (int mi = 0; mi < 2; mi++) {
                uint32_t off = SWZ((uint32_t)((a_row + mi * 16) * 128 +
                                              (kb + a_koff) * 2));
                ldm_x4(a[mi], stA + off);
            }
            uint32_t b[2][4];
            #pragma unroll
            for (int pi = 0; pi < 2; pi++) {
                uint32_t off = SWZ((uint32_t)((b_row + pi * 16) * 128 +
                                              (kb + b_koff) * 2));
                ldm_x4(b[pi], stB + off);
            }
            #pragma unroll
            for (int mi = 0; mi < 2; mi++)
                #pragma unroll
                for (int ni = 0; ni < 4; ni++)
                    mma16816(acc[mi][ni], a[mi],
                             b[ni >> 1][(ni & 1) * 2],
                             b[ni >> 1][(ni & 1) * 2 + 1]);
        }
        __syncthreads();
    }

    // ---- epilogue ----
    const int grp = lane >> 2, tig = lane & 3;
    const int rbase = row0 + wm * 32 + grp;
    const int cbase = col0 + wn * 32 + tig * 2;
    #pragma unroll
    for (int mi = 0; mi < 2; mi++) {
        #pragma unroll
        for (int ni = 0; ni < 4; ni++) {
            const int cc = cbase + ni * 8;
            const int r1 = rbase + mi * 16, r2 = r1 + 8;
            float* f = acc[mi][ni];
            if (EPI == EPI_BF16) {
                bf16* o = (bf16*)Cout;
                *(__nv_bfloat162*)&o[(size_t)r1 * Nout + cc] =
                    __floats2bfloat162_rn(f[0], f[1]);
                *(__nv_bfloat162*)&o[(size_t)r2 * Nout + cc] =
                    __floats2bfloat162_rn(f[2], f[3]);
            } else if (EPI == EPI_SCALE) {
                float* o = (float*)Cout;
                *(float2*)&o[(size_t)r1 * Nout + cc] =
                    make_float2(alpha * f[0], alpha * f[1]);
                *(float2*)&o[(size_t)r2 * Nout + cc] =
                    make_float2(alpha * f[2], alpha * f[3]);
            } else {
                float* o = (float*)Cout;
                float2 x = *(const float2*)&Cadd[(size_t)r1 * Nout + cc];
                float2 y = *(const float2*)&Cadd[(size_t)r2 * Nout + cc];
                *(float2*)&o[(size_t)r1 * Nout + cc] =
                    make_float2(f[0] + x.x, f[1] + x.y);
                *(float2*)&o[(size_t)r2 * Nout + cc] =
                    make_float2(f[2] + y.x, f[3] + y.y);
            }
        }
    }
}

// ---------------------------------------------------------------------------
// prep kernels
// ---------------------------------------------------------------------------
// Convert joint (BB*DD) and conf (KK*DD) in a single launch.
__global__ void cvt_joint_conf(const float* __restrict__ joint,
                               const float* __restrict__ conf,
                               bf16* __restrict__ jh, bf16* __restrict__ ch)
{
    int i = (blockIdx.x * blockDim.x + threadIdx.x) * 4;
    const int N1 = BB * DD;
    const float* in;
    bf16* out;
    int idx;
    if (i < N1) { in = joint; out = jh; idx = i; }
    else        { in = conf;  out = ch; idx = i - N1; }
    float4 v = *(const float4*)&in[idx];
    *(__nv_bfloat162*)&out[idx]     = __floats2bfloat162_rn(v.x, v.y);
    *(__nv_bfloat162*)&out[idx + 2] = __floats2bfloat162_rn(v.z, v.w);
}

// Transpose + convert both weight matrices in one launch (z selects Wq/Wk).
// out[c*R + r] = (bf16) in[r*C + c],  R=DD, C=PP
__global__ void transpose_cvt2(const float* __restrict__ Wq,
                               const float* __restrict__ Wk,
                               bf16* __restrict__ wqt, bf16* __restrict__ wkt)
{
    __shared__ float t[32][33];
    const float* in = blockIdx.z ? Wk : Wq;
    bf16* out       = blockIdx.z ? wkt : wqt;
    const int C = PP, R = DD;
    const int c0 = blockIdx.x * 32, r0 = blockIdx.y * 32;
    #pragma unroll
    for (int j = 0; j < 32; j += 8)
        t[threadIdx.y + j][threadIdx.x] =
            in[(size_t)(r0 + threadIdx.y + j) * C + c0 + threadIdx.x];
    __syncthreads();
    #pragma unroll
    for (int j = 0; j < 32; j += 8)
        out[(size_t)(c0 + threadIdx.y + j) * R + r0 + threadIdx.x] =
            __float2bfloat16(t[threadIdx.x][threadIdx.y + j]);
}

// (conf * prior)^T -> bf16:  out[d*KK + k] = conf[k*DD + d] * prior[k]
__global__ void cpt_kernel(const float* __restrict__ conf,
                           const float* __restrict__ prior,
                           bf16* __restrict__ out)
{
    __shared__ float t[32][33];
    const int d0 = blockIdx.x * 32, k0 = blockIdx.y * 32;
    #pragma unroll
    for (int j = 0; j < 32; j += 8) {
        int k = k0 + threadIdx.y + j;
        t[threadIdx.y + j][threadIdx.x] =
            conf[(size_t)k * DD + d0 + threadIdx.x] * prior[k];
    }
    __syncthreads();
    #pragma unroll
    for (int j = 0; j < 32; j += 8)
        out[(size_t)(d0 + threadIdx.y + j) * KK + k0 + threadIdx.x] =
            __float2bfloat16(t[threadIdx.x][threadIdx.y + j]);
}

// Row softmax over K=256 (fp32 in, bf16 out). One block per row.
__global__ __launch_bounds__(256) void softmax_rows(const float* __restrict__ s,
                                                    bf16* __restrict__ a)
{
    const int b = blockIdx.x;
    const int t = threadIdx.x;
    __shared__ float red[8];
    __shared__ float bcast;

    float v = s[(size_t)b * KK + t];

    float m = v;
    #pragma unroll
    for (int o = 16; o; o >>= 1) m = fmaxf(m, __shfl_xor_sync(~0u, m, o));
    if ((t & 31) == 0) red[t >> 5] = m;
    __syncthreads();
    if (t == 0) {
        float x = red[0];
        #pragma unroll
        for (int w = 1; w < 8; w++) x = fmaxf(x, red[w]);
        bcast = x;
    }
    __syncthreads();
    const float rowmax = bcast;

    float e = __expf(v - rowmax);

    float sm = e;
    #pragma unroll
    for (int o = 16; o; o >>= 1) sm += __shfl_xor_sync(~0u, sm, o);
    if ((t & 31) == 0) red[t >> 5] = sm;
    __syncthreads();
    if (t == 0) {
        float x = 0.f;
        #pragma unroll
        for (int w = 0; w < 8; w++) x += red[w];
        bcast = x;
    }
    __syncthreads();

    a[(size_t)b * KK + t] = __float2bfloat16(e / bcast);
}

// ---------------------------------------------------------------------------
extern "C" void kernel_launch(void* const* d_in, const int* in_sizes, int n_in,
                              void* d_out, int out_size)
{
    const float* joint = (const float*)d_in[0];   // [1024,1024]
    const float* conf  = (const float*)d_in[1];   // [256,1024]
    const float* prior = (const float*)d_in[2];   // [256,1]
    const float* Wq    = (const float*)d_in[3];   // [1024,768]
    const float* Wk    = (const float*)d_in[4];   // [1024,768]
    float* out = (float*)d_out;                   // [1024,1024]

    bf16 *jh, *ch, *wqt, *wkt, *cpt, *qh, *kh, *ah; float* s;
    cudaGetSymbolAddress((void**)&jh,  g_jh);
    cudaGetSymbolAddress((void**)&ch,  g_ch);
    cudaGetSymbolAddress((void**)&wqt, g_wqt);
    cudaGetSymbolAddress((void**)&wkt, g_wkt);
    cudaGetSymbolAddress((void**)&cpt, g_cpt);
    cudaGetSymbolAddress((void**)&qh,  g_qh);
    cudaGetSymbolAddress((void**)&kh,  g_kh);
    cudaGetSymbolAddress((void**)&s,   g_s);
    cudaGetSymbolAddress((void**)&ah,  g_ah);

    const int SMEM = 2 * STAGE_BYTES;  // 32 KB

    // --- prep: bf16 conversions / transposes (3 launches) ---
    cvt_joint_conf<<<(BB * DD + KK * DD) / 1024, 256>>>(joint, conf, jh, ch);
    transpose_cvt2<<<dim3(PP / 32, DD / 32, 2), dim3(32, 8)>>>(Wq, Wk, wqt, wkt);
    cpt_kernel<<<dim3(DD / 32, KK / 32), dim3(32, 8)>>>(conf, prior, cpt);

    // --- q = joint @ Wq        grid 12x16 = 192 CTAs ---
    gemm_mma<EPI_BF16><<<dim3(PP / 64, BB / 64), 128, SMEM>>>(
        jh, wqt, nullptr, qh, DD, PP, DD / 64, 1.f);
    // --- k = conf @ Wk         grid 12x4 = 48 CTAs ---
    gemm_mma<EPI_BF16><<<dim3(PP / 64, KK / 64), 128, SMEM>>>(
        ch, wkt, nullptr, kh, DD, PP, DD / 64, 1.f);
    // --- scores = (q @ k^T)/32 grid 4x16 = 64 CTAs ---
    gemm_mma<EPI_SCALE><<<dim3(KK / 64, BB / 64), 128, SMEM>>>(
        qh, kh, nullptr, s, PP, KK, PP / 64, 1.f / 32.f);
    // --- softmax rows (fp32 -> bf16 attn) ---
    softmax_rows<<<BB, 256>>>(s, ah);
    // --- out = attn @ (conf*prior) + joint   grid 16x16 = 256 CTAs ---
    gemm_mma<EPI_ADD><<<dim3(DD / 64, BB / 64), 128, SMEM>>>(
        ah, cpt, joint, out, KK, DD, KK / 64, 1.f);
}